// round 14
// baseline (speedup 1.0000x reference)
#include <cuda_runtime.h>
#include <cuda_fp16.h>
#include <cstdint>

#define L_LEN  16384
#define CIN    64
#define NB     64
#define NOC    36
#define NOCP   40
#define MT     512
#define ROWS   526
#define NT     (NB * (L_LEN / MT)) // 2048 tiles
#define NTHR   512                 // 16 warps, warp M=32

#define W_OFF       0
#define W_BYTES     76800          // [15 taps][40 oc][64 ch] fp16
#define X0_OFF      76800
#define XBUF_BYTES  (ROWS * 128)   // 67328
#define SMEM_TOTAL  (W_BYTES + 2 * XBUF_BYTES)   // 211456

#define SWZ(o) ((o) ^ (((o) >> 3) & 0x70))

// first active n8-tile per tap
__device__ constexpr int JMIN[15] = {3,3,2,2,1,0,0,0,0,0,1,2,2,3,3};

__device__ __half g_xh[(size_t)NB * L_LEN * CIN];

__device__ __forceinline__ uint32_t smem_u32(const void* p) {
    uint32_t a;
    asm("{ .reg .u64 t; cvta.to.shared.u64 t, %1; cvt.u32.u64 %0, t; }"
        : "=r"(a) : "l"(p));
    return a;
}

__device__ __forceinline__ void ldsm_x4(uint32_t* r, uint32_t addr) {
    asm volatile("ldmatrix.sync.aligned.m8n8.x4.shared.b16 {%0,%1,%2,%3}, [%4];"
                 : "=r"(r[0]), "=r"(r[1]), "=r"(r[2]), "=r"(r[3]) : "r"(addr));
}
__device__ __forceinline__ void ldsm_x2(uint32_t* r, uint32_t addr) {
    asm volatile("ldmatrix.sync.aligned.m8n8.x2.shared.b16 {%0,%1}, [%2];"
                 : "=r"(r[0]), "=r"(r[1]) : "r"(addr));
}
__device__ __forceinline__ void mma4(float* d, uint32_t a0, uint32_t a1,
                                     uint32_t a2, uint32_t a3,
                                     uint32_t b0, uint32_t b1) {
    asm volatile(
        "mma.sync.aligned.m16n8k16.row.col.f32.f16.f16.f32 "
        "{%0,%1,%2,%3}, {%4,%5,%6,%7}, {%8,%9}, {%0,%1,%2,%3};"
        : "+f"(d[0]), "+f"(d[1]), "+f"(d[2]), "+f"(d[3])
        : "r"(a0), "r"(a1), "r"(a2), "r"(a3), "r"(b0), "r"(b1));
}

// ---------------------------------------------------------------------------
// Prepass: x [b][c][l] fp32 -> g_xh [b][l][c] fp16, granule-permuted.
// ---------------------------------------------------------------------------
__global__ void __launch_bounds__(256)
prepass(const float* __restrict__ x)
{
    __shared__ float t[64][257];
    const int tid = threadIdx.x;
    const int l0  = blockIdx.x * 256;
    const int b   = blockIdx.y;
    const float4* xb4 = reinterpret_cast<const float4*>(
        x + (size_t)b * CIN * L_LEN + l0);

#pragma unroll
    for (int i = 0; i < 16; i++) {
        int f  = i * 256 + tid;
        int c  = f >> 6;
        int l4 = f & 63;
        float4 v = xb4[(size_t)c * (L_LEN / 4) + l4];
        t[c][4 * l4 + 0] = v.x;
        t[c][4 * l4 + 1] = v.y;
        t[c][4 * l4 + 2] = v.z;
        t[c][4 * l4 + 3] = v.w;
    }
    __syncthreads();

    const int g  = tid & 7;
    const int lb = tid >> 3;
#pragma unroll
    for (int p = 0; p < 8; p++) {
        int lloc = lb + p * 32;
        int l    = l0 + lloc;
        int perm = (l + 7) & 7;
        int c0   = ((g ^ perm) << 3);
        uint32_t r[4];
#pragma unroll
        for (int u = 0; u < 4; u++) {
            __half2 h = __floats2half2_rn(t[c0 + 2 * u][lloc],
                                          t[c0 + 2 * u + 1][lloc]);
            r[u] = *reinterpret_cast<uint32_t*>(&h);
        }
        reinterpret_cast<uint4*>(g_xh + (((size_t)(b * L_LEN + l)) << 6))[g] =
            make_uint4(r[0], r[1], r[2], r[3]);
    }
}

// ---------------------------------------------------------------------------
// Async staging of one x tile.
// ---------------------------------------------------------------------------
__device__ __forceinline__ void stage_tile_async(uint32_t dstbase,
                                                 const __half* xh_b, int P0)
{
    for (int g2 = threadIdx.x; g2 < ROWS * 8; g2 += NTHR) {
        int q = g2 >> 3, g = g2 & 7;
        int l = P0 - 7 + q;
        uint32_t dst = dstbase + (uint32_t)(q * 128 + g * 16);
        if ((unsigned)l < (unsigned)L_LEN) {
            const void* src = xh_b + (((size_t)l << 6) + (g << 3));
            asm volatile("cp.async.cg.shared.global [%0], [%1], 16;"
                         :: "r"(dst), "l"(src));
        } else {
            asm volatile("st.shared.v4.b32 [%0], {%1,%1,%1,%1};"
                         :: "r"(dst), "r"(0u));
        }
    }
    asm volatile("cp.async.commit_group;" ::: "memory");
}

__global__ void __launch_bounds__(NTHR, 1)
conv_hmma(float* __restrict__ out,
          const float* __restrict__ w1,  const float* __restrict__ b1,
          const float* __restrict__ w3,  const float* __restrict__ b3,
          const float* __restrict__ w5,  const float* __restrict__ b5,
          const float* __restrict__ w7,  const float* __restrict__ b7,
          const float* __restrict__ w9,  const float* __restrict__ b9,
          const float* __restrict__ w11, const float* __restrict__ b11,
          const float* __restrict__ w13, const float* __restrict__ b13,
          const float* __restrict__ w15, const float* __restrict__ b15)
{
    extern __shared__ char sm[];
    __shared__ float sbias[NOCP];

    const int tid  = threadIdx.x;
    const int lane = tid & 31;
    const int wid  = tid >> 5;
    const int wbase = wid << 5;          // warp rows [wbase, wbase+32)
    const int grp  = lane >> 2;
    const int qd   = lane & 3;
    const uint32_t laneRA = lane & 15;
    const uint32_t laneKA = (uint32_t)(lane >> 4) << 4;
    const uint32_t laneR2 = lane & 7;                        // x2: 8 rows
    const uint32_t laneK2 = (uint32_t)((lane >> 3) & 1) << 4; // x2: k chunk
    const uint32_t laneRB = lane & 7;
    const uint32_t laneKB = (uint32_t)(lane >> 3) << 4;
    const uint32_t smb = smem_u32(sm);
    const uint32_t wsm = smb + W_OFF;

    // ---- zero W + bias ----
    for (int i = tid; i < W_BYTES / 4; i += NTHR)
        reinterpret_cast<uint32_t*>(sm + W_OFF)[i] = 0u;
    if (tid < NOCP) sbias[tid] = 0.f;
    __syncthreads();

    // ---- fill W (fp16, [t][oc][c], SW128) + bias ----
    {
        const float* ws[8] = {w1, w3, w5, w7, w9, w11, w13, w15};
        const float* bs[8] = {b1, b3, b5, b7, b9, b11, b13, b15};
        for (int g = 0; g < 8; g++) {
            const int k   = 2 * g + 1;
            const int cnt = g ? 5 : 1;
            const int oc0 = g ? (1 + 5 * (g - 1)) : 0;
            const int tot = cnt * CIN * k;
            const float* wg = ws[g];
            for (int i = tid; i < tot; i += NTHR) {
                int j  = i % k;
                int c  = (i / k) % CIN;
                int ol = i / (k * CIN);
                int t  = 7 - g + j;
                uint32_t o = SWZ((uint32_t)((t * NOCP + oc0 + ol) * 128 + c * 2));
                *reinterpret_cast<__half*>(sm + W_OFF + o) = __float2half_rn(wg[i]);
            }
        }
        if (tid < NOC) {
            int oc = tid;
            int g  = oc ? (oc - 1) / 5 + 1 : 0;
            int ol = oc ? (oc - 1) % 5 : 0;
            sbias[oc] = bs[g][ol];
        }
    }

    // ---- stage first tile into buffer 0 (async) ----
    stage_tile_async(smb + X0_OFF,
                     g_xh + ((size_t)(blockIdx.x >> 5) * L_LEN << 6),
                     (blockIdx.x & 31) << 9);
    __syncthreads();

    int it = 0;
    for (int tile = blockIdx.x; tile < NT; tile += gridDim.x, it++) {
        const int buf = it & 1;
        const uint32_t xbase = smb + X0_OFF + buf * XBUF_BYTES;

        const int ntile = tile + gridDim.x;
        const bool hn = ntile < NT;

        if (hn)
            stage_tile_async(smb + X0_OFF + (buf ^ 1) * XBUF_BYTES,
                             g_xh + ((size_t)(ntile >> 5) * L_LEN << 6),
                             (ntile & 31) << 9);

        if (hn) asm volatile("cp.async.wait_group 1;" ::: "memory");
        else    asm volatile("cp.async.wait_group 0;" ::: "memory");
        __syncthreads();

        float acc[2][5][4];
#pragma unroll
        for (int j = 0; j < 5; j++) {
            float v0 = sbias[8 * j + 2 * qd];
            float v1 = sbias[8 * j + 2 * qd + 1];
#pragma unroll
            for (int mt = 0; mt < 2; mt++) {
                acc[mt][j][0] = v0;
                acc[mt][j][1] = v1;
                acc[mt][j][2] = v0;
                acc[mt][j][3] = v1;
            }
        }

        // ---- tap pairs (p, p+8): A fragments of tap p+8 are register
        //      aliases of tap p's blocks (row shift 8), plus one x2 load ----
#pragma unroll
        for (int p = 0; p < 7; p++) {
            const int jmL = JMIN[p];
            const int jmH = JMIN[p + 8];

            // preload B for both taps of the pair (<= 56 regs)
            uint32_t bL[5][8], bH[5][8];
#pragma unroll
            for (int j = 0; j < 5; j++) {
                if (j >= jmL) {
                    uint32_t o = (uint32_t)(p * NOCP + j * 8 + laneRB) * 128 + laneKB;
                    ldsm_x4(bL[j],     wsm + SWZ(o));
                    ldsm_x4(bL[j] + 4, wsm + SWZ(o + 64));
                }
                if (j >= jmH) {
                    uint32_t o = (uint32_t)((p + 8) * NOCP + j * 8 + laneRB) * 128 + laneKB;
                    ldsm_x4(bH[j],     wsm + SWZ(o));
                    ldsm_x4(bH[j] + 4, wsm + SWZ(o + 64));
                }
            }

#pragma unroll
            for (int kt = 0; kt < 4; kt++) {
                uint32_t A0[4], A1[4], A2[2];
                {
                    uint32_t o0 = (uint32_t)(wbase + p + laneRA) * 128
                                + (uint32_t)kt * 32 + laneKA;
                    uint32_t o1 = (uint32_t)(wbase + 16 + p + laneRA) * 128
                                + (uint32_t)kt * 32 + laneKA;
                    uint32_t o2 = (uint32_t)(wbase + 32 + p + laneR2) * 128
                                + (uint32_t)kt * 32 + laneK2;
                    ldsm_x4(A0, xbase + SWZ(o0));
                    ldsm_x4(A1, xbase + SWZ(o1));
                    ldsm_x2(A2, xbase + SWZ(o2));
                }
                // tap p
#pragma unroll
                for (int j = 0; j < 5; j++) {
                    if (j < jmL) continue;
                    mma4(acc[0][j], A0[0], A0[1], A0[2], A0[3],
                         bL[j][2 * kt], bL[j][2 * kt + 1]);
                    mma4(acc[1][j], A1[0], A1[1], A1[2], A1[3],
                         bL[j][2 * kt], bL[j][2 * kt + 1]);
                }
                // tap p+8 (aliased fragments, rows +8)
#pragma unroll
                for (int j = 0; j < 5; j++) {
                    if (j < jmH) continue;
                    mma4(acc[0][j], A0[1], A1[0], A0[3], A1[2],
                         bH[j][2 * kt], bH[j][2 * kt + 1]);
                    mma4(acc[1][j], A1[1], A2[0], A1[3], A2[1],
                         bH[j][2 * kt], bH[j][2 * kt + 1]);
                }
            }
        }

        // ---- tap 7 (unpaired, jm = 0) ----
        {
            uint32_t b7r[5][8];
#pragma unroll
            for (int j = 0; j < 5; j++) {
                uint32_t o = (uint32_t)(7 * NOCP + j * 8 + laneRB) * 128 + laneKB;
                ldsm_x4(b7r[j],     wsm + SWZ(o));
                ldsm_x4(b7r[j] + 4, wsm + SWZ(o + 64));
            }
#pragma unroll
            for (int kt = 0; kt < 4; kt++) {
                uint32_t A0[4], A1[4];
                uint32_t o0 = (uint32_t)(wbase + 7 + laneRA) * 128
                            + (uint32_t)kt * 32 + laneKA;
                uint32_t o1 = (uint32_t)(wbase + 16 + 7 + laneRA) * 128
                            + (uint32_t)kt * 32 + laneKA;
                ldsm_x4(A0, xbase + SWZ(o0));
                ldsm_x4(A1, xbase + SWZ(o1));
#pragma unroll
                for (int j = 0; j < 5; j++) {
                    mma4(acc[0][j], A0[0], A0[1], A0[2], A0[3],
                         b7r[j][2 * kt], b7r[j][2 * kt + 1]);
                    mma4(acc[1][j], A1[0], A1[1], A1[2], A1[3],
                         b7r[j][2 * kt], b7r[j][2 * kt + 1]);
                }
            }
        }

        // epilogue
        const int b_ = tile >> 5;
        const int P0 = (tile & 31) << 9;
#pragma unroll
        for (int mt = 0; mt < 2; mt++) {
            const int m = P0 + wbase + mt * 16 + grp;
#pragma unroll
            for (int j = 0; j < 5; j++) {
                const int n0 = 8 * j + 2 * qd;
                float* o0 = out + ((size_t)b_ * NOC + n0) * L_LEN + m;
                if (n0 < NOC) {
                    o0[0] = acc[mt][j][0];
                    o0[8] = acc[mt][j][2];
                }
                if (n0 + 1 < NOC) {
                    float* o1 = o0 + L_LEN;
                    o1[0] = acc[mt][j][1];
                    o1[8] = acc[mt][j][3];
                }
            }
        }
        __syncthreads();
    }
}

extern "C" void kernel_launch(void* const* d_in, const int* in_sizes, int n_in,
                              void* d_out, int out_size)
{
    const float* x = (const float*)d_in[0];

    prepass<<<dim3(L_LEN / 256, NB), 256>>>(x);

    cudaFuncSetAttribute(conv_hmma, cudaFuncAttributeMaxDynamicSharedMemorySize,
                         SMEM_TOTAL);
    int nsm = 148;
    cudaDeviceGetAttribute(&nsm, cudaDevAttrMultiProcessorCount, 0);
    if (nsm > NT) nsm = NT;

    conv_hmma<<<nsm, NTHR, SMEM_TOTAL>>>(
        (float*)d_out,
        (const float*)d_in[1],  (const float*)d_in[2],
        (const float*)d_in[3],  (const float*)d_in[4],
        (const float*)d_in[5],  (const float*)d_in[6],
        (const float*)d_in[7],  (const float*)d_in[8],
        (const float*)d_in[9],  (const float*)d_in[10],
        (const float*)d_in[11], (const float*)d_in[12],
        (const float*)d_in[13], (const float*)d_in[14],
        (const float*)d_in[15], (const float*)d_in[16]);
}

// round 15
// speedup vs baseline: 1.0980x; 1.0980x over previous
#include <cuda_runtime.h>
#include <cuda_fp16.h>
#include <cstdint>

#define L_LEN  16384
#define CIN    64
#define NB     64
#define NOC    36
#define NOCP   40
#define MT     512
#define ROWS   526
#define NT     (NB * (L_LEN / MT)) // 2048 tiles
#define NTHR   512                 // 16 warps, warp M=32

#define W_OFF       0
#define W_BYTES     76800          // [15 taps][40 oc][64 ch] fp16
#define X0_OFF      76800
#define XBUF_BYTES  (ROWS * 128)   // 67328
#define SMEM_TOTAL  (W_BYTES + 2 * XBUF_BYTES)   // 211456

#define SWZ(o) ((o) ^ (((o) >> 3) & 0x70))

// first active n8-tile per tap
__device__ constexpr int JMIN[15] = {3,3,2,2,1,0,0,0,0,0,1,2,2,3,3};

__device__ __forceinline__ uint32_t smem_u32(const void* p) {
    uint32_t a;
    asm("{ .reg .u64 t; cvta.to.shared.u64 t, %1; cvt.u32.u64 %0, t; }"
        : "=r"(a) : "l"(p));
    return a;
}

__device__ __forceinline__ void ldsm_x4(uint32_t* r, uint32_t addr) {
    asm volatile("ldmatrix.sync.aligned.m8n8.x4.shared.b16 {%0,%1,%2,%3}, [%4];"
                 : "=r"(r[0]), "=r"(r[1]), "=r"(r[2]), "=r"(r[3]) : "r"(addr));
}
__device__ __forceinline__ void mma16816(float* d, const uint32_t* a, const uint32_t* b) {
    asm volatile(
        "mma.sync.aligned.m16n8k16.row.col.f32.f16.f16.f32 "
        "{%0,%1,%2,%3}, {%4,%5,%6,%7}, {%8,%9}, {%0,%1,%2,%3};"
        : "+f"(d[0]), "+f"(d[1]), "+f"(d[2]), "+f"(d[3])
        : "r"(a[0]), "r"(a[1]), "r"(a[2]), "r"(a[3]), "r"(b[0]), "r"(b[1]));
}

// stage one item (4 channels x 1 row) of a tile into smem fp16 (SW128)
__device__ __forceinline__ void stage_item(char* dst, const float* xb, int P0, int gi)
{
    if (gi >= 16 * ROWS) return;               // 8416 items
    int q  = gi % ROWS;
    int cq = gi / ROWS;
    int l  = P0 - 7 + q;
    float v0 = 0.f, v1 = 0.f, v2 = 0.f, v3 = 0.f;
    if ((unsigned)l < (unsigned)L_LEN) {
        const float* p = xb + (size_t)cq * 4 * L_LEN + l;
        v0 = __ldg(p);
        v1 = __ldg(p + L_LEN);
        v2 = __ldg(p + 2 * L_LEN);
        v3 = __ldg(p + 3 * L_LEN);
    }
    __half2 h01 = __floats2half2_rn(v0, v1);
    __half2 h23 = __floats2half2_rn(v2, v3);
    uint32_t o = SWZ((uint32_t)(q * 128 + cq * 8));
    uint2 val;
    val.x = *reinterpret_cast<uint32_t*>(&h01);
    val.y = *reinterpret_cast<uint32_t*>(&h23);
    *reinterpret_cast<uint2*>(dst + o) = val;
}

__device__ __forceinline__ void stage_tile(char* dst, const float* xb, int P0, int tid)
{
#pragma unroll
    for (int i = 0; i < 17; i++)
        stage_item(dst, xb, P0, i * NTHR + tid);
}

__global__ void __launch_bounds__(NTHR, 1)
conv_hmma(const float* __restrict__ x, float* __restrict__ out,
          const float* __restrict__ w1,  const float* __restrict__ b1,
          const float* __restrict__ w3,  const float* __restrict__ b3,
          const float* __restrict__ w5,  const float* __restrict__ b5,
          const float* __restrict__ w7,  const float* __restrict__ b7,
          const float* __restrict__ w9,  const float* __restrict__ b9,
          const float* __restrict__ w11, const float* __restrict__ b11,
          const float* __restrict__ w13, const float* __restrict__ b13,
          const float* __restrict__ w15, const float* __restrict__ b15)
{
    extern __shared__ char sm[];
    __shared__ float sbias[NOCP];

    const int tid  = threadIdx.x;
    const int lane = tid & 31;
    const int wid  = tid >> 5;
    const int wbase = wid << 5;          // warp rows [wbase, wbase+32)
    const int grp  = lane >> 2;
    const int qd   = lane & 3;
    const uint32_t laneRA = lane & 15;
    const uint32_t laneKA = (uint32_t)(lane >> 4) << 4;
    const uint32_t laneRB = lane & 7;
    const uint32_t laneKB = (uint32_t)(lane >> 3) << 4;
    const uint32_t smb = smem_u32(sm);
    const uint32_t wsm = smb + W_OFF;

    // ---- zero W + bias ----
    for (int i = tid; i < W_BYTES / 4; i += NTHR)
        reinterpret_cast<uint32_t*>(sm + W_OFF)[i] = 0u;
    if (tid < NOCP) sbias[tid] = 0.f;
    __syncthreads();

    // ---- fill W (fp16, [t][oc][c], SW128) + bias ----
    {
        const float* ws[8] = {w1, w3, w5, w7, w9, w11, w13, w15};
        const float* bs[8] = {b1, b3, b5, b7, b9, b11, b13, b15};
        for (int g = 0; g < 8; g++) {
            const int k   = 2 * g + 1;
            const int cnt = g ? 5 : 1;
            const int oc0 = g ? (1 + 5 * (g - 1)) : 0;
            const int tot = cnt * CIN * k;
            const float* wg = ws[g];
            for (int i = tid; i < tot; i += NTHR) {
                int j  = i % k;
                int c  = (i / k) % CIN;
                int ol = i / (k * CIN);
                int t  = 7 - g + j;
                uint32_t o = SWZ((uint32_t)((t * NOCP + oc0 + ol) * 128 + c * 2));
                *reinterpret_cast<__half*>(sm + W_OFF + o) = __float2half_rn(wg[i]);
            }
        }
        if (tid < NOC) {
            int oc = tid;
            int g  = oc ? (oc - 1) / 5 + 1 : 0;
            int ol = oc ? (oc - 1) % 5 : 0;
            sbias[oc] = bs[g][ol];
        }
    }

    // ---- stage first tile into buffer 0 ----
    stage_tile(sm + X0_OFF,
               x + (size_t)(blockIdx.x >> 5) * CIN * L_LEN,
               (blockIdx.x & 31) << 9, tid);
    __syncthreads();

    float bj[5][2];
#pragma unroll
    for (int j = 0; j < 5; j++) {
        bj[j][0] = sbias[8 * j + 2 * qd];
        bj[j][1] = sbias[8 * j + 2 * qd + 1];
    }

    int it = 0;
    for (int tile = blockIdx.x; tile < NT; tile += gridDim.x, it++) {
        const int buf = it & 1;
        const uint32_t xbase = smb + X0_OFF + buf * XBUF_BYTES;

        const int ntile = tile + gridDim.x;
        const bool hn = ntile < NT;

        // stage NEXT tile into the other buffer (fp32 LDG -> cvt -> STS.64;
        // 17 independent items per thread give deep MLP; the previous
        // iteration's end barrier guarantees buf^1 readers are done)
        if (hn)
            stage_tile(sm + X0_OFF + (buf ^ 1) * XBUF_BYTES,
                       x + (size_t)(ntile >> 5) * CIN * L_LEN,
                       (ntile & 31) << 9, tid);

        float acc[2][5][4];
#pragma unroll
        for (int mt = 0; mt < 2; mt++)
#pragma unroll
            for (int j = 0; j < 5; j++) {
                acc[mt][j][0] = bj[j][0];
                acc[mt][j][1] = bj[j][1];
                acc[mt][j][2] = bj[j][0];
                acc[mt][j][3] = bj[j][1];
            }

#pragma unroll
        for (int t = 0; t < 15; t++) {
            const int jm = JMIN[t];

            // preload ALL B fragments for this tap once
            uint32_t b[5][8];
#pragma unroll
            for (int j = 0; j < 5; j++) {
                if (j < jm) continue;
                uint32_t o = (uint32_t)(t * NOCP + j * 8 + laneRB) * 128 + laneKB;
                ldsm_x4(b[j],     wsm + SWZ(o));        // k 0..31
                ldsm_x4(b[j] + 4, wsm + SWZ(o + 64));   // k 32..63
            }

#pragma unroll
            for (int kt = 0; kt < 4; kt++) {
                uint32_t a4[2][4];
#pragma unroll
                for (int mt = 0; mt < 2; mt++) {
                    uint32_t o = (uint32_t)(wbase + mt * 16 + t + laneRA) * 128
                               + (uint32_t)kt * 32 + laneKA;
                    ldsm_x4(a4[mt], xbase + SWZ(o));
                }
#pragma unroll
                for (int j = 0; j < 5; j++) {
                    if (j < jm) continue;
#pragma unroll
                    for (int mt = 0; mt < 2; mt++)
                        mma16816(acc[mt][j], a4[mt], b[j] + 2 * kt);
                }
            }
        }

        // epilogue
        const int b_ = tile >> 5;
        const int P0 = (tile & 31) << 9;
#pragma unroll
        for (int mt = 0; mt < 2; mt++) {
            const int m = P0 + wbase + mt * 16 + grp;
#pragma unroll
            for (int j = 0; j < 5; j++) {
                const int n0 = 8 * j + 2 * qd;
                float* o0 = out + ((size_t)b_ * NOC + n0) * L_LEN + m;
                if (n0 < NOC) {
                    o0[0] = acc[mt][j][0];
                    o0[8] = acc[mt][j][2];
                }
                if (n0 + 1 < NOC) {
                    float* o1 = o0 + L_LEN;
                    o1[0] = acc[mt][j][1];
                    o1[8] = acc[mt][j][3];
                }
            }
        }
        __syncthreads();   // staging of buf^1 done; reads of buf done
    }
}

extern "C" void kernel_launch(void* const* d_in, const int* in_sizes, int n_in,
                              void* d_out, int out_size)
{
    cudaFuncSetAttribute(conv_hmma, cudaFuncAttributeMaxDynamicSharedMemorySize,
                         SMEM_TOTAL);
    int nsm = 148;
    cudaDeviceGetAttribute(&nsm, cudaDevAttrMultiProcessorCount, 0);
    if (nsm > NT) nsm = NT;

    conv_hmma<<<nsm, NTHR, SMEM_TOTAL>>>(
        (const float*)d_in[0], (float*)d_out,
        (const float*)d_in[1],  (const float*)d_in[2],
        (const float*)d_in[3],  (const float*)d_in[4],
        (const float*)d_in[5],  (const float*)d_in[6],
        (const float*)d_in[7],  (const float*)d_in[8],
        (const float*)d_in[9],  (const float*)d_in[10],
        (const float*)d_in[11], (const float*)d_in[12],
        (const float*)d_in[13], (const float*)d_in[14],
        (const float*)d_in[15], (const float*)d_in[16]);
}